// round 1
// baseline (speedup 1.0000x reference)
#include <cuda_runtime.h>
#include <cstdint>
#include <cstddef>

// Problem shapes (fixed)
#define Tt   512
#define Bb   16
#define Dd   512
#define Hh   1024
#define G2   2048            // 2*H
#define NB   128             // persistent blocks (<= SM count, 1 block/SM)
#define JPB  8               // h columns per block (Hh / NB)
#define STR  1028            // smem row stride in floats (padded)
#define LN_EPS 1e-5f

// ---------------- device scratch (allocation-free) ----------------
__device__ float    g_w[(size_t)Bb * Tt * G2];   // 64 MB: LN'd projection
__device__ float    g_hbuf[2][Bb * Hh];          // double-buffered hidden state
__device__ unsigned g_arrive[NB];
__device__ unsigned g_release;

// ---------------- init: reset barrier state + h0 ----------------
__global__ void init_state_k(const float* __restrict__ h0) {
    int i = blockIdx.x * blockDim.x + threadIdx.x;
    if (i < Bb * Hh) g_hbuf[0][i] = h0[i & (Hh - 1)];   // broadcast h0 over batch
    if (i < NB)      g_arrive[i] = 0u;
    if (i == 0)      g_release = 0u;
}

// ---------------- phase 1: g_w = x @ W^T  (fp32 tiled GEMM) ----------------
// C[8192][2048] = X[8192][512] * W[2048][512]^T
__global__ void __launch_bounds__(256) gemm_xw_k(const float* __restrict__ X,
                                                 const float* __restrict__ W) {
    __shared__ float As[16][64];
    __shared__ float Bs[16][64];
    int bx = blockIdx.x;          // n tile (32)
    int by = blockIdx.y;          // m tile (128)
    int tid = threadIdx.x;
    int tx = tid & 15;            // n sub
    int ty = tid >> 4;            // m sub
    int lr = tid >> 2;            // 0..63 row within tile
    int lc = (tid & 3) << 2;      // 0,4,8,12 col within k-tile

    const float* Xp = X + (size_t)(by * 64 + lr) * Dd + lc;
    const float* Wp = W + (size_t)(bx * 64 + lr) * Dd + lc;

    float acc[4][4];
#pragma unroll
    for (int i = 0; i < 4; ++i)
#pragma unroll
        for (int j = 0; j < 4; ++j) acc[i][j] = 0.f;

    for (int k0 = 0; k0 < Dd; k0 += 16) {
        float4 xa = *(const float4*)(Xp + k0);
        float4 wa = *(const float4*)(Wp + k0);
        As[lc + 0][lr] = xa.x; As[lc + 1][lr] = xa.y;
        As[lc + 2][lr] = xa.z; As[lc + 3][lr] = xa.w;
        Bs[lc + 0][lr] = wa.x; Bs[lc + 1][lr] = wa.y;
        Bs[lc + 2][lr] = wa.z; Bs[lc + 3][lr] = wa.w;
        __syncthreads();
#pragma unroll
        for (int kk = 0; kk < 16; ++kk) {
            float4 av = *(const float4*)(&As[kk][ty * 4]);
            float4 bv = *(const float4*)(&Bs[kk][tx * 4]);
            float a[4] = {av.x, av.y, av.z, av.w};
            float b[4] = {bv.x, bv.y, bv.z, bv.w};
#pragma unroll
            for (int i = 0; i < 4; ++i)
#pragma unroll
                for (int j = 0; j < 4; ++j)
                    acc[i][j] = fmaf(a[i], b[j], acc[i][j]);
        }
        __syncthreads();
    }
#pragma unroll
    for (int i = 0; i < 4; ++i) {
        float4 v = make_float4(acc[i][0], acc[i][1], acc[i][2], acc[i][3]);
        size_t row = (size_t)(by * 64 + ty * 4 + i);
        *(float4*)(g_w + row * G2 + bx * 64 + tx * 4) = v;
    }
}

// ---------------- phase 2: in-place rowwise LayerNorm over 2H ----------------
__global__ void __launch_bounds__(256) ln_rows_k(const float* __restrict__ gamma,
                                                 const float* __restrict__ beta) {
    int row = blockIdx.x;
    float* p = g_w + (size_t)row * G2;
    int tid = threadIdx.x;

    float4 v0 = *(const float4*)(p + tid * 4);
    float4 v1 = *(const float4*)(p + 1024 + tid * 4);
    float s  = v0.x + v0.y + v0.z + v0.w + v1.x + v1.y + v1.z + v1.w;
    float s2 = v0.x*v0.x + v0.y*v0.y + v0.z*v0.z + v0.w*v0.w
             + v1.x*v1.x + v1.y*v1.y + v1.z*v1.z + v1.w*v1.w;

#pragma unroll
    for (int o = 16; o > 0; o >>= 1) {
        s  += __shfl_xor_sync(0xFFFFFFFFu, s,  o);
        s2 += __shfl_xor_sync(0xFFFFFFFFu, s2, o);
    }
    __shared__ float rs[8], rs2[8];
    __shared__ float mean_s, inv_s;
    int wid = tid >> 5;
    if ((tid & 31) == 0) { rs[wid] = s; rs2[wid] = s2; }
    __syncthreads();
    if (tid == 0) {
        float S = 0.f, S2 = 0.f;
#pragma unroll
        for (int w = 0; w < 8; ++w) { S += rs[w]; S2 += rs2[w]; }
        float m  = S * (1.f / G2);
        float var = S2 * (1.f / G2) - m * m;
        mean_s = m;
        inv_s = rsqrtf(var + LN_EPS);
    }
    __syncthreads();
    float m = mean_s, inv = inv_s;

    float4 g0v = *(const float4*)(gamma + tid * 4);
    float4 b0v = *(const float4*)(beta  + tid * 4);
    float4 g1v = *(const float4*)(gamma + 1024 + tid * 4);
    float4 b1v = *(const float4*)(beta  + 1024 + tid * 4);
    float4 o0, o1;
    o0.x = (v0.x - m) * inv * g0v.x + b0v.x;
    o0.y = (v0.y - m) * inv * g0v.y + b0v.y;
    o0.z = (v0.z - m) * inv * g0v.z + b0v.z;
    o0.w = (v0.w - m) * inv * g0v.w + b0v.w;
    o1.x = (v1.x - m) * inv * g1v.x + b1v.x;
    o1.y = (v1.y - m) * inv * g1v.y + b1v.y;
    o1.z = (v1.z - m) * inv * g1v.z + b1v.z;
    o1.w = (v1.w - m) * inv * g1v.w + b1v.w;
    *(float4*)(p + tid * 4)        = o0;
    *(float4*)(p + 1024 + tid * 4) = o1;
}

// ---------------- phase 3: persistent recurrence ----------------
// Block `bid` owns h columns [bid*8, bid*8+8) and U rows {j.. , 1024+j..}.
// One software global barrier per timestep; double-buffered h makes it safe.
__global__ void __launch_bounds__(256, 1) ligru_rec_k(const float* __restrict__ U,
                                                      float* __restrict__ out) {
    extern __shared__ float sm[];
    float* Us    = sm;                     // 16 * STR
    float* hs    = sm + 16 * STR;          // 16 * STR
    float* red   = hs + 16 * STR;          // 1024
    float* gates = red + 1024;             // 16 * 17

    int tid = threadIdx.x;
    int bid = blockIdx.x;
    int jbase = bid * JPB;

    // Load U slice into SMEM (rows 0..7 = a-rows, 8..15 = z-rows), once.
#pragma unroll 1
    for (int r = 0; r < 16; ++r) {
        int grow = (r < 8) ? (jbase + r) : (Hh + jbase + (r - 8));
        float4 v = *(const float4*)(U + (size_t)grow * Hh + tid * 4);
        float* dst = Us + r * STR + tid * 4;
        dst[0] = v.x; dst[1] = v.y; dst[2] = v.z; dst[3] = v.w;
    }

    // Thread decomposition: 4 k-quarters x 8 b-pairs x 8 g-pairs
    int q   = tid >> 6;         // k quarter
    int r2  = tid & 63;
    int tb2 = r2 & 7;           // b pair
    int tg2 = r2 >> 3;          // g pair
    int b0  = tb2 * 2;
    int g0  = tg2 * 2;
    int kbase = q * 256;

    // gates-pass role
    int wb = tid >> 4;          // batch 0..15
    int wg = tid & 15;          // gate row 0..15
    int wcol = (wg < 8) ? (jbase + wg) : (Hh + jbase + (wg - 8));

    __syncthreads();  // Us ready

    unsigned buf = 0;
    for (int t = 0; t < Tt; ++t) {
        if (t > 0) {
            if (tid == 0) {
                while (*(volatile unsigned*)&g_release < (unsigned)t) { }
            }
            __syncthreads();
        }

        // Prefetch this step's w value (used ~4k cycles later in gates pass)
        float wv = __ldg(g_w + (size_t)(wb * Tt + t) * G2 + wcol);

        // Load my k-quarter of h (all 16 batches) into SMEM; L2-only (L1 stale)
        {
            const float* hsrc = g_hbuf[buf];
            int c = kbase + (r2 << 2);
#pragma unroll
            for (int bb = 0; bb < 16; ++bb) {
                float4 v = __ldcg((const float4*)(hsrc + bb * Hh + c));
                *(float4*)(hs + bb * STR + c) = v;
            }
        }
        __syncthreads();  // hs ready (also orders vs prev-step epilogue reads)

        // Register-tiled partial dots: 2b x 2g over 256 k
        float c00 = 0.f, c01 = 0.f, c10 = 0.f, c11 = 0.f;
        {
            const float* hp0 = hs + b0 * STR;
            const float* hp1 = hp0 + STR;
            const float* up0 = Us + g0 * STR;
            const float* up1 = up0 + STR;
#pragma unroll 4
            for (int k = kbase; k < kbase + 256; k += 4) {
                float4 hv0 = *(const float4*)(hp0 + k);
                float4 hv1 = *(const float4*)(hp1 + k);
                float4 uv0 = *(const float4*)(up0 + k);
                float4 uv1 = *(const float4*)(up1 + k);
                c00 = fmaf(hv0.x, uv0.x, c00); c00 = fmaf(hv0.y, uv0.y, c00);
                c00 = fmaf(hv0.z, uv0.z, c00); c00 = fmaf(hv0.w, uv0.w, c00);
                c01 = fmaf(hv0.x, uv1.x, c01); c01 = fmaf(hv0.y, uv1.y, c01);
                c01 = fmaf(hv0.z, uv1.z, c01); c01 = fmaf(hv0.w, uv1.w, c01);
                c10 = fmaf(hv1.x, uv0.x, c10); c10 = fmaf(hv1.y, uv0.y, c10);
                c10 = fmaf(hv1.z, uv0.z, c10); c10 = fmaf(hv1.w, uv0.w, c10);
                c11 = fmaf(hv1.x, uv1.x, c11); c11 = fmaf(hv1.y, uv1.y, c11);
                c11 = fmaf(hv1.z, uv1.z, c11); c11 = fmaf(hv1.w, uv1.w, c11);
            }
        }
        {
            int ridx = ((q * 8 + tb2) * 8 + tg2) * 4;
            red[ridx + 0] = c00;   // [bi=0][gi=0]
            red[ridx + 1] = c01;   // [bi=0][gi=1]
            red[ridx + 2] = c10;   // [bi=1][gi=0]
            red[ridx + 3] = c11;   // [bi=1][gi=1]
        }
        __syncthreads();

        // Gates pass: sum 4 k-quarter partials + w
        {
            int sub = (wb & 1) * 2 + (wg & 1);
            int base = ((wb >> 1) * 8 + (wg >> 1)) * 4 + sub;
            float dot = red[base] + red[base + 256] + red[base + 512] + red[base + 768];
            gates[wg * 17 + wb] = wv + dot;
        }
        __syncthreads();

        // Combine: h update for my 8 columns x 16 batches
        if (tid < 128) {
            int b  = tid >> 3;
            int jl = tid & 7;
            float a  = gates[jl * 17 + b];
            float zg = gates[(8 + jl) * 17 + b];
            float z  = 1.f / (1.f + expf(-zg));
            float hold = hs[b * STR + jbase + jl];
            float hn = z * hold + (1.f - z) * fmaxf(a, 0.f);
            g_hbuf[buf ^ 1u][b * Hh + jbase + jl] = hn;
            out[(size_t)b * (Tt * Hh) + (size_t)t * Hh + jbase + jl] = hn;
        }
        __threadfence();
        __syncthreads();

        // Arrive
        if (tid == 0) ((volatile unsigned*)g_arrive)[bid] = (unsigned)(t + 1);

        // Block 0 gathers and releases
        if (bid == 0) {
            if (tid < NB) {
                while (((volatile unsigned*)g_arrive)[tid] < (unsigned)(t + 1)) { }
            }
            __syncthreads();
            if (tid == 0) {
                __threadfence();
                *(volatile unsigned*)&g_release = (unsigned)(t + 1);
            }
        }
        buf ^= 1u;
    }
}

// ---------------- launch ----------------
extern "C" void kernel_launch(void* const* d_in, const int* in_sizes, int n_in,
                              void* d_out, int out_size) {
    const float* x     = (const float*)d_in[0];   // [16,512,512]
    const float* W_w   = (const float*)d_in[1];   // [2048,512]
    const float* U_w   = (const float*)d_in[2];   // [2048,1024]
    const float* gamma = (const float*)d_in[3];   // [2048]
    const float* beta  = (const float*)d_in[4];   // [2048]
    const float* h0    = (const float*)d_in[5];   // [1,1024]
    float* out = (float*)d_out;                   // [16,512,1024]

    const int smem_rec = (2 * 16 * STR + 1024 + 16 * 17 + 16) * (int)sizeof(float);
    cudaFuncSetAttribute(ligru_rec_k, cudaFuncAttributeMaxDynamicSharedMemorySize,
                         smem_rec);

    init_state_k<<<64, 256>>>(h0);

    dim3 gg(G2 / 64, (Bb * Tt) / 64);
    gemm_xw_k<<<gg, 256>>>(x, W_w);

    ln_rows_k<<<Bb * Tt, 256>>>(gamma, beta);

    ligru_rec_k<<<NB, 256, smem_rec>>>(U_w, out);
}